// round 1
// baseline (speedup 1.0000x reference)
#include <cuda_runtime.h>

// CTC forward loss, faithful to keras ctc_batch_cost + tf v1 ctc_loss.
// B=128 batches, T=1024 timesteps, C=128 classes (blank = C-1), L=128 labels,
// S = 2L+1 = 257 lattice states.
//
// One CTA per batch element. 288 threads (9 warps): threads 0..256 own lattice
// states; threads 0..127 also load/normalize the per-timestep class row.
// Single __syncthreads per timestep via double-buffered lpc/wsum/alpha.
// Per-timestep log-normalizer (log softmax denominator) is deferred: LSE is
// shift-equivariant, so we run the DP on log(p+eps) and subtract sum(logZ_t)
// once at the end (accumulated by thread 0 only).

#define T_    1024
#define C_    128
#define L_    128
#define S_    257
#define BLANK 127
#define EPS_  1e-7f
#define NEG_  -1e30f
#define NTH   288

__global__ __launch_bounds__(NTH, 1)
void ctc_fwd_kernel(const int* __restrict__ y_true,
                    const float* __restrict__ y_pred,
                    float* __restrict__ out)
{
    const int b    = blockIdx.x;
    const int tid  = threadIdx.x;
    const int lane = tid & 31;
    const int wrp  = tid >> 5;

    __shared__ float lpc[2][C_];        // log(p+eps) per class, double-buffered
    __shared__ float wsum[2][4];        // per-warp partial sums of p
    __shared__ float alpha[2][S_ + 3];  // [0..1] = NEG pad, states at +2
    __shared__ int   labels[L_];

    if (tid < L_) labels[tid] = y_true[b * L_ + tid];
    if (tid < 2) { alpha[0][tid] = NEG_; alpha[1][tid] = NEG_; }
    __syncthreads();

    // Per-thread lattice-state config.
    const int  s      = tid;
    const bool active = (s < S_);
    int  cls = BLANK;
    bool canskip = false;
    if (active && (s & 1)) {
        const int li = s >> 1;        // label index for odd state
        cls = labels[li];
        if (li >= 1) canskip = (cls != labels[li - 1]);
    }

    const float* __restrict__ row = y_pred + (size_t)b * T_ * C_;

    // 4-deep register prefetch pipeline (only tid < C_ loads).
    float p0 = 0.f, p1 = 0.f, p2 = 0.f, p3 = 0.f;
    if (tid < C_) {
        p0 = row[0 * C_ + tid];
        p1 = row[1 * C_ + tid];
        p2 = row[2 * C_ + tid];
        p3 = row[3 * C_ + tid];
    }

    float myA     = NEG_;  // alpha[s] for my state (un-normalized domain)
    float logZsum = 0.f;   // thread 0 only

    // ---------------- t = 0: init ----------------
    {
        float p = p0;
        p0 = p1; p1 = p2; p2 = p3;
        if (tid < C_) {
            p3 = row[4 * C_ + tid];
            float v = p;
            #pragma unroll
            for (int off = 16; off; off >>= 1)
                v += __shfl_xor_sync(0xffffffffu, v, off);
            if (lane == 0) wsum[0][wrp] = v;
            lpc[0][tid] = __logf(p + EPS_);
        }
        __syncthreads();
        if (tid == 0)
            logZsum = __logf(wsum[0][0] + wsum[0][1] + wsum[0][2] + wsum[0][3]
                             + (float)C_ * EPS_);
        if (active) {
            myA = (s < 2) ? lpc[0][cls] : NEG_;
            alpha[0][2 + s] = myA;
        }
    }

    // ---------------- t = 1 .. T-1 ----------------
    for (int t = 1; t < T_; ++t) {
        const int buf = t & 1;
        const int ob  = buf ^ 1;

        // stage 1: class-row load + per-warp sum + log(p+eps)
        float p = p0;
        p0 = p1; p1 = p2; p2 = p3;
        if (tid < C_) {
            if (t + 4 < T_) p3 = row[(t + 4) * C_ + tid];
            float v = p;
            #pragma unroll
            for (int off = 16; off; off >>= 1)
                v += __shfl_xor_sync(0xffffffffu, v, off);
            if (lane == 0) wsum[buf][wrp] = v;
            lpc[buf][tid] = __logf(p + EPS_);
        }
        __syncthreads();

        if (tid == 0)
            logZsum += __logf(wsum[buf][0] + wsum[buf][1] + wsum[buf][2] + wsum[buf][3]
                              + (float)C_ * EPS_);

        // stage 2: DP update alpha_new[s] = LSE(a[s], a[s-1], a[s-2]?) + lp[cls]
        if (active) {
            const float lp     = lpc[buf][cls];
            const float a_stay = myA;
            const float a_prev = alpha[ob][2 + s - 1];
            const float a_skip = canskip ? alpha[ob][2 + s - 2] : NEG_;
            const float m = fmaxf(a_stay, fmaxf(a_prev, a_skip));
            const float e = __expf(a_stay - m) + __expf(a_prev - m) + __expf(a_skip - m);
            myA = m + __logf(e) + lp;
            alpha[buf][2 + s] = myA;
        }
    }

    __syncthreads();
    if (tid == 0) {
        const int buf = (T_ - 1) & 1;
        const float a = alpha[buf][2 + S_ - 1];
        const float c = alpha[buf][2 + S_ - 2];
        const float m = fmaxf(a, c);
        const float ll = m + __logf(__expf(a - m) + __expf(c - m)) - logZsum;
        out[b] = -ll;
    }
}

extern "C" void kernel_launch(void* const* d_in, const int* in_sizes, int n_in,
                              void* d_out, int out_size)
{
    const int* y_true;
    const float* y_pred;
    if (in_sizes[0] == L_ * 128) {          // y_true: [B, L] int32
        y_true = (const int*)d_in[0];
        y_pred = (const float*)d_in[1];
    } else {
        y_true = (const int*)d_in[1];
        y_pred = (const float*)d_in[0];
    }
    const int B = out_size;                  // [B,1] float32 output
    ctc_fwd_kernel<<<B, NTH>>>(y_true, y_pred, (float*)d_out);
}

// round 3
// speedup vs baseline: 5.0187x; 5.0187x over previous
#include <cuda_runtime.h>

// CTC forward loss — linear-domain DP with PER-LANE block-floating-point scaling.
// B=128, T=1024, C=128 (blank=127), L=128, S=257.
//
// One CTA (64 threads) per batch element.
//   warp 0: the sequential DP. Lane l owns states 8l..8l+7 (+ state 256 on
//           lane 31). true_alpha = a * 2^e, e per-lane int exponent.
//           Cross-lane handoff rebases scales with exact power-of-2 factors.
//           Lane renormalizes to its own max every 2nd step.
//   warp 1: softmax log-normalizer zsum = sum_t log(sum_c p + C*eps),
//           independent of the DP; handed over via shared memory at the end.
//
// loglik = log(a255+a256) + e_lane31*ln2 - zsum ; out = -loglik.

#define T_   1024
#define C_   128
#define L_   128
#define EPS_ 1e-7f
#define CEPS_ (128.0f * 1e-7f)
#define FULL 0xffffffffu

// One DP timestep. PH = t&7 (compile-time). RS=1 -> renormalize lane scale.
#define STEP(PH, t, RS) {                                                      \
    float pb   = __shfl_sync(FULL, pbc, (t) & 31) + EPS_;                      \
    float a7up = __shfl_up_sync(FULL, a7, 1);                                  \
    int   e_up = __shfl_up_sync(FULL, e, 1);                                   \
    float a255 = __shfl_sync(FULL, a7, 31);                                    \
    int dd  = e_up - e;                                                        \
    int bpm = 127 + min(dd, 0);                                                \
    int bsa = 127 - max(dd, 0);                                                \
    float sc_pm = (bpm >= 1) ? __int_as_float(bpm << 23) : 0.f;                \
    float sc_a  = (bsa >= 1) ? __int_as_float(bsa << 23) : 0.f;                \
    e = max(e, e_up);                                                          \
    float pm1 = lane0 ? 0.f : a7up * sc_pm;                                    \
    a0 *= sc_a; a1 *= sc_a; a2 *= sc_a; a3 *= sc_a;                            \
    a4 *= sc_a; a5 *= sc_a; a6 *= sc_a; a7 *= sc_a; a256 *= sc_a;              \
    float q0 = gbr[PH][0] + EPS_; float q1 = gbr[PH][1] + EPS_;                \
    float q2 = gbr[PH][2] + EPS_; float q3 = gbr[PH][3] + EPS_;                \
    if ((t) + 8 < T_) {                                                        \
        const float* r8 = row + (size_t)((t) + 8) * C_;                        \
        gbr[PH][0] = r8[cls0]; gbr[PH][1] = r8[cls1];                          \
        gbr[PH][2] = r8[cls2]; gbr[PH][3] = r8[cls3];                          \
    }                                                                          \
    float n0 = (a0 + pm1) * pb;                                                \
    float n1 = fmaf(sk0, pm1, a1 + a0) * q0;                                   \
    float n2 = (a2 + a1) * pb;                                                 \
    float n3 = fmaf(sk1, a1, a3 + a2) * q1;                                    \
    float n4 = (a4 + a3) * pb;                                                 \
    float n5 = fmaf(sk2, a3, a5 + a4) * q2;                                    \
    float n6 = (a6 + a5) * pb;                                                 \
    float n7 = fmaf(sk3, a5, a7 + a6) * q3;                                    \
    float n8 = (a256 + a255 * sc_a) * pb;                                      \
    if (RS) {                                                                  \
        float m = fmaxf(fmaxf(fmaxf(n0, n1), fmaxf(n2, n3)),                   \
                        fmaxf(fmaxf(n4, n5), fmaxf(n6, n7)));                  \
        m = fmaxf(m, p31 ? n8 : 0.f);                                          \
        int k = (__float_as_int(m) >> 23) - 127;                               \
        float sck = __int_as_float((127 - k) << 23);                           \
        e += k;                                                                \
        a0 = n0 * sck; a1 = n1 * sck; a2 = n2 * sck; a3 = n3 * sck;            \
        a4 = n4 * sck; a5 = n5 * sck; a6 = n6 * sck; a7 = n7 * sck;            \
        a256 = n8 * sck;                                                       \
    } else {                                                                   \
        a0 = n0; a1 = n1; a2 = n2; a3 = n3;                                    \
        a4 = n4; a5 = n5; a6 = n6; a7 = n7; a256 = n8;                         \
    } }

#define BLOCK8(tb) \
    STEP(0, (tb) + 0, 0) STEP(1, (tb) + 1, 1) STEP(2, (tb) + 2, 0) \
    STEP(3, (tb) + 3, 1) STEP(4, (tb) + 4, 0) STEP(5, (tb) + 5, 1) \
    STEP(6, (tb) + 6, 0) STEP(7, (tb) + 7, 1)

__global__ __launch_bounds__(64, 1)
void ctc_bfp_kernel(const int* __restrict__ y_true,
                    const float* __restrict__ y_pred,
                    float* __restrict__ out)
{
    const int b    = blockIdx.x;
    const int tid  = threadIdx.x;
    const int lane = tid & 31;
    const int wrp  = tid >> 5;
    const float* __restrict__ row = y_pred + (size_t)b * T_ * C_;

    __shared__ float s_zsum;

    if (wrp == 1) {
        // -------- softmax log-normalizer over all T rows --------
        float zs = 0.f;
        for (int t8 = 0; t8 < T_; t8 += 8) {
            float zp = 1.f;
            #pragma unroll
            for (int j = 0; j < 8; j++) {
                float4 v = *(const float4*)(row + (size_t)(t8 + j) * C_ + 4 * lane);
                float z = (v.x + v.y) + (v.z + v.w);
                z += __shfl_xor_sync(FULL, z, 1);
                z += __shfl_xor_sync(FULL, z, 2);
                z += __shfl_xor_sync(FULL, z, 4);
                z += __shfl_xor_sync(FULL, z, 8);
                z += __shfl_xor_sync(FULL, z, 16);
                zp *= (z + CEPS_);
            }
            zs += __logf(zp);
        }
        if (lane == 0) s_zsum = zs;
    } else {
        // -------- sequential DP warp --------
        const bool lane0 = (lane == 0);
        const bool p31   = (lane == 31);

        int4 c4 = *(const int4*)(y_true + b * L_ + 4 * lane);
        const int cls0 = c4.x, cls1 = c4.y, cls2 = c4.z, cls3 = c4.w;
        int clsm1 = __shfl_up_sync(FULL, cls3, 1);
        const float sk0 = (lane > 0 && cls0 != clsm1) ? 1.f : 0.f;
        const float sk1 = (cls1 != cls0) ? 1.f : 0.f;
        const float sk2 = (cls2 != cls1) ? 1.f : 0.f;
        const float sk3 = (cls3 != cls2) ? 1.f : 0.f;

        // blank-prob block buffers: lane l holds p_blank at t = block_base + l
        float pbc = row[(size_t)lane * C_ + (C_ - 1)];
        float pbn = row[(size_t)(32 + lane) * C_ + (C_ - 1)];

        // gather ring, depth 8: gbr[t&7] = p[t, cls0..3]
        float gbr[8][4];
        #pragma unroll
        for (int j = 0; j < 8; j++) {
            const float* r = row + (size_t)j * C_;
            gbr[j][0] = r[cls0]; gbr[j][1] = r[cls1];
            gbr[j][2] = r[cls2]; gbr[j][3] = r[cls3];
        }

        float a0 = 0.f, a1 = 0.f, a2 = 0.f, a3 = 0.f,
              a4 = 0.f, a5 = 0.f, a6 = 0.f, a7 = 0.f, a256 = 0.f;
        int e = 0;

        // ---- t = 0 init: states 0 (blank) and 1 (first label) ----
        {
            float pb0 = __shfl_sync(FULL, pbc, 0) + EPS_;
            float g0  = gbr[0][0];
            const float* r8 = row + (size_t)8 * C_;   // refill slot 0 with row 8
            gbr[0][0] = r8[cls0]; gbr[0][1] = r8[cls1];
            gbr[0][2] = r8[cls2]; gbr[0][3] = r8[cls3];
            if (lane0) { a0 = pb0; a1 = g0 + EPS_; }
        }

        // ---- t = 1..7 prologue ----
        STEP(1, 1, 1) STEP(2, 2, 0) STEP(3, 3, 1) STEP(4, 4, 0)
        STEP(5, 5, 1) STEP(6, 6, 0) STEP(7, 7, 1)

        // ---- t = 8..1023 ----
        for (int tb = 8; tb < T_; tb += 8) {
            if ((tb & 31) == 0) {
                pbc = pbn;
                if (tb + 32 < T_)
                    pbn = row[(size_t)(tb + 32 + lane) * C_ + (C_ - 1)];
            }
            BLOCK8(tb)
        }
        // keep lane-31 results live in a7/a256/e for the epilogue below
    }

    __syncthreads();
    if (wrp == 0 && lane == 31) {
        // a7 = alpha[255], a256 = alpha[256], both at scale 2^e (lane 31).
        // NOTE: these registers survive from the else-branch above.
    }
    // epilogue must be outside divergent region for clean codegen:
    if (tid == 31) {
        // recompute nothing: thread 31 is warp 0 lane 31
        extern __shared__ float _dummy[];  // (unused) keep compiler happy
    }
    __syncthreads();
    // Final write (warp 0, lane 31 holds the state):
    // done here via a second pass:
    return;
}

// The epilogue above got awkward with macro scoping — use a cleaner kernel:
__global__ __launch_bounds__(64, 1)
void ctc_bfp_kernel2(const int* __restrict__ y_true,
                     const float* __restrict__ y_pred,
                     float* __restrict__ out)
{
    const int b    = blockIdx.x;
    const int tid  = threadIdx.x;
    const int lane = tid & 31;
    const int wrp  = tid >> 5;
    const float* __restrict__ row = y_pred + (size_t)b * T_ * C_;

    __shared__ float s_zsum;

    float fin_a = 0.f, fin_c = 0.f;
    int   fin_e = 0;

    if (wrp == 1) {
        float zs = 0.f;
        for (int t8 = 0; t8 < T_; t8 += 8) {
            float zp = 1.f;
            #pragma unroll
            for (int j = 0; j < 8; j++) {
                float4 v = *(const float4*)(row + (size_t)(t8 + j) * C_ + 4 * lane);
                float z = (v.x + v.y) + (v.z + v.w);
                z += __shfl_xor_sync(FULL, z, 1);
                z += __shfl_xor_sync(FULL, z, 2);
                z += __shfl_xor_sync(FULL, z, 4);
                z += __shfl_xor_sync(FULL, z, 8);
                z += __shfl_xor_sync(FULL, z, 16);
                zp *= (z + CEPS_);
            }
            zs += __logf(zp);
        }
        if (lane == 0) s_zsum = zs;
    } else {
        const bool lane0 = (lane == 0);
        const bool p31   = (lane == 31);

        int4 c4 = *(const int4*)(y_true + b * L_ + 4 * lane);
        const int cls0 = c4.x, cls1 = c4.y, cls2 = c4.z, cls3 = c4.w;
        int clsm1 = __shfl_up_sync(FULL, cls3, 1);
        const float sk0 = (lane > 0 && cls0 != clsm1) ? 1.f : 0.f;
        const float sk1 = (cls1 != cls0) ? 1.f : 0.f;
        const float sk2 = (cls2 != cls1) ? 1.f : 0.f;
        const float sk3 = (cls3 != cls2) ? 1.f : 0.f;

        float pbc = row[(size_t)lane * C_ + (C_ - 1)];
        float pbn = row[(size_t)(32 + lane) * C_ + (C_ - 1)];

        float gbr[8][4];
        #pragma unroll
        for (int j = 0; j < 8; j++) {
            const float* r = row + (size_t)j * C_;
            gbr[j][0] = r[cls0]; gbr[j][1] = r[cls1];
            gbr[j][2] = r[cls2]; gbr[j][3] = r[cls3];
        }

        float a0 = 0.f, a1 = 0.f, a2 = 0.f, a3 = 0.f,
              a4 = 0.f, a5 = 0.f, a6 = 0.f, a7 = 0.f, a256 = 0.f;
        int e = 0;

        {
            float pb0 = __shfl_sync(FULL, pbc, 0) + EPS_;
            float g0  = gbr[0][0];
            const float* r8 = row + (size_t)8 * C_;
            gbr[0][0] = r8[cls0]; gbr[0][1] = r8[cls1];
            gbr[0][2] = r8[cls2]; gbr[0][3] = r8[cls3];
            if (lane0) { a0 = pb0; a1 = g0 + EPS_; }
        }

        STEP(1, 1, 1) STEP(2, 2, 0) STEP(3, 3, 1) STEP(4, 4, 0)
        STEP(5, 5, 1) STEP(6, 6, 0) STEP(7, 7, 1)

        for (int tb = 8; tb < T_; tb += 8) {
            if ((tb & 31) == 0) {
                pbc = pbn;
                if (tb + 32 < T_)
                    pbn = row[(size_t)(tb + 32 + lane) * C_ + (C_ - 1)];
            }
            BLOCK8(tb)
        }

        fin_a = a7;      // alpha[255] on lane 31
        fin_c = a256;    // alpha[256] on lane 31
        fin_e = e;
    }

    __syncthreads();
    if (wrp == 0 && lane == 31) {
        float ll = __logf(fin_a + fin_c) + (float)fin_e * 0.6931471805599453f
                   - s_zsum;
        out[b] = -ll;
    }
}

extern "C" void kernel_launch(void* const* d_in, const int* in_sizes, int n_in,
                              void* d_out, int out_size)
{
    const int* y_true;
    const float* y_pred;
    if (in_sizes[0] == 128 * L_) {            // y_true: [B,L] int32
        y_true = (const int*)d_in[0];
        y_pred = (const float*)d_in[1];
    } else {
        y_true = (const int*)d_in[1];
        y_pred = (const float*)d_in[0];
    }
    const int B = out_size;                    // [B,1] float32
    ctc_bfp_kernel2<<<B, 64>>>(y_true, y_pred, (float*)d_out);
}

// round 4
// speedup vs baseline: 5.0564x; 1.0075x over previous
#include <cuda_runtime.h>

// CTC forward loss — linear-domain DP, per-lane block-floating-point scaling,
// incoming-edge-only rescale (no per-step self-rebase), renorm every 4 steps.
// B=128, T=1024, C=128 (blank=127), L=128, S=257.
//
// One CTA (64 threads) per batch element.
//   warp 0: sequential DP. Lane l owns states 8l..8l+7; state 256 lives on
//           lane 31 only (alpha[255] is lane 31's own a7 — no broadcast).
//           true_alpha = a * 2^e (e per-lane). Cross-lane value is rescaled to
//           the receiver's exponent: pm1 = a7up * 2^(e_up - e), clamped.
//           Empty lanes adopt the neighbor exponent at renorm steps.
//   warp 1: softmax log-normalizer zsum = sum_t log(sum_c p + C*eps).
//
// loglik = log(a255 + a256) + e*ln2 - zsum  (lane 31);  out = -loglik.

#define T_   1024
#define C_   128
#define L_   128
#define EPS_ 1e-7f
#define CEPS_ (128.0f * 1e-7f)
#define FULL 0xffffffffu

// One DP timestep. PH = t&7 (compile-time ring slot). RS=1 -> renormalize.
#define STEP(PH, t, RS) {                                                      \
    float pb   = __shfl_sync(FULL, pbc, (t) & 31);                             \
    float a7up = __shfl_up_sync(FULL, a7, 1);                                  \
    int   e_up = __shfl_up_sync(FULL, e, 1);                                   \
    int bexp = min(max(e_up - e + 127, 0), 254);                               \
    if (lane == 0) bexp = 0;                                                   \
    float pm1 = a7up * __int_as_float(bexp << 23);                             \
    float q0 = gbr[PH][0], q1 = gbr[PH][1],                                    \
          q2 = gbr[PH][2], q3 = gbr[PH][3];                                    \
    if ((t) + 8 < T_) {                                                        \
        const float* r8 = row + (size_t)((t) + 8) * C_;                        \
        gbr[PH][0] = r8[cls0] + EPS_; gbr[PH][1] = r8[cls1] + EPS_;            \
        gbr[PH][2] = r8[cls2] + EPS_; gbr[PH][3] = r8[cls3] + EPS_;            \
    }                                                                          \
    float n0 = (a0 + pm1) * pb;                                                \
    float n1 = fmaf(sk0, pm1, a1 + a0) * q0;                                   \
    float n2 = (a2 + a1) * pb;                                                 \
    float n3 = fmaf(sk1, a1, a3 + a2) * q1;                                    \
    float n4 = (a4 + a3) * pb;                                                 \
    float n5 = fmaf(sk2, a3, a5 + a4) * q2;                                    \
    float n6 = (a6 + a5) * pb;                                                 \
    float n7 = fmaf(sk3, a5, a7 + a6) * q3;                                    \
    float n8 = (a256 + a7) * pb;          /* lane 31: a7 == alpha[255] */      \
    if (RS) {                                                                  \
        float m = fmaxf(fmaxf(fmaxf(n0, n1), fmaxf(n2, n3)),                   \
                        fmaxf(fmaxf(n4, n5), fmaxf(n6, n7)));                  \
        if (lane == 31) m = fmaxf(m, n8);                                      \
        const bool has = (m > 0.f);                                            \
        const int k = has ? ((__float_as_int(m) >> 23) - 127) : 0;             \
        e = has ? (e + k) : e_up;         /* empty lane: adopt neighbor */     \
        const float sck = __int_as_float((127 - k) << 23);                     \
        a0 = n0 * sck; a1 = n1 * sck; a2 = n2 * sck; a3 = n3 * sck;            \
        a4 = n4 * sck; a5 = n5 * sck; a6 = n6 * sck; a7 = n7 * sck;            \
        a256 = n8 * sck;                                                       \
    } else {                                                                   \
        a0 = n0; a1 = n1; a2 = n2; a3 = n3;                                    \
        a4 = n4; a5 = n5; a6 = n6; a7 = n7; a256 = n8;                         \
    } }

#define BLOCK8(tb) \
    STEP(0, (tb) + 0, 0) STEP(1, (tb) + 1, 0) STEP(2, (tb) + 2, 0) \
    STEP(3, (tb) + 3, 1) STEP(4, (tb) + 4, 0) STEP(5, (tb) + 5, 0) \
    STEP(6, (tb) + 6, 0) STEP(7, (tb) + 7, 1)

__global__ __launch_bounds__(64, 1)
void ctc_bfp4_kernel(const int* __restrict__ y_true,
                     const float* __restrict__ y_pred,
                     float* __restrict__ out)
{
    const int b    = blockIdx.x;
    const int tid  = threadIdx.x;
    const int lane = tid & 31;
    const int wrp  = tid >> 5;
    const float* __restrict__ row = y_pred + (size_t)b * T_ * C_;

    __shared__ float s_zsum;

    float fin_a = 0.f, fin_c = 0.f;
    int   fin_e = 0;

    if (wrp == 1) {
        // -------- softmax log-normalizer, independent of the DP --------
        float zs = 0.f;
        for (int t8 = 0; t8 < T_; t8 += 8) {
            float zp = 1.f;
            #pragma unroll
            for (int j = 0; j < 8; j++) {
                float4 v = *(const float4*)(row + (size_t)(t8 + j) * C_ + 4 * lane);
                float z = (v.x + v.y) + (v.z + v.w);
                z += __shfl_xor_sync(FULL, z, 1);
                z += __shfl_xor_sync(FULL, z, 2);
                z += __shfl_xor_sync(FULL, z, 4);
                z += __shfl_xor_sync(FULL, z, 8);
                z += __shfl_xor_sync(FULL, z, 16);
                zp *= (z + CEPS_);       // Z ~ 64 per step; 8 steps < fp32 max
            }
            zs += __logf(zp);
        }
        if (lane == 0) s_zsum = zs;
    } else {
        // -------- sequential DP warp --------
        int4 c4 = *(const int4*)(y_true + b * L_ + 4 * lane);
        const int cls0 = c4.x, cls1 = c4.y, cls2 = c4.z, cls3 = c4.w;
        int clsm1 = __shfl_up_sync(FULL, cls3, 1);
        const float sk0 = (lane > 0 && cls0 != clsm1) ? 1.f : 0.f;
        const float sk1 = (cls1 != cls0) ? 1.f : 0.f;
        const float sk2 = (cls2 != cls1) ? 1.f : 0.f;
        const float sk3 = (cls3 != cls2) ? 1.f : 0.f;

        // blank-prob ring: lane l holds (p_blank + eps) at t = base + l
        float pbc = row[(size_t)lane * C_ + (C_ - 1)] + EPS_;
        float pbn = row[(size_t)(32 + lane) * C_ + (C_ - 1)] + EPS_;

        // gather ring, depth 8: gbr[t&7] = p[t, cls0..3] + eps
        float gbr[8][4];
        #pragma unroll
        for (int j = 0; j < 8; j++) {
            const float* r = row + (size_t)j * C_;
            gbr[j][0] = r[cls0] + EPS_; gbr[j][1] = r[cls1] + EPS_;
            gbr[j][2] = r[cls2] + EPS_; gbr[j][3] = r[cls3] + EPS_;
        }

        float a0 = 0.f, a1 = 0.f, a2 = 0.f, a3 = 0.f,
              a4 = 0.f, a5 = 0.f, a6 = 0.f, a7 = 0.f, a256 = 0.f;
        int e = 0;

        // ---- t = 0 init: states 0 (blank) and 1 (first label) ----
        {
            float pb0 = __shfl_sync(FULL, pbc, 0);
            float g0  = gbr[0][0];
            const float* r8 = row + (size_t)8 * C_;   // refill slot 0
            gbr[0][0] = r8[cls0] + EPS_; gbr[0][1] = r8[cls1] + EPS_;
            gbr[0][2] = r8[cls2] + EPS_; gbr[0][3] = r8[cls3] + EPS_;
            if (lane == 0) { a0 = pb0; a1 = g0; }
        }

        // ---- t = 1..7 prologue (renorm at t=3,7 -> t == 3 mod 4) ----
        STEP(1, 1, 0) STEP(2, 2, 0) STEP(3, 3, 1) STEP(4, 4, 0)
        STEP(5, 5, 0) STEP(6, 6, 0) STEP(7, 7, 1)

        // ---- t = 8..1023 ----
        for (int tb = 8; tb < T_; tb += 8) {
            if ((tb & 31) == 0) {
                pbc = pbn;
                if (tb + 32 < T_)
                    pbn = row[(size_t)(tb + 32 + lane) * C_ + (C_ - 1)] + EPS_;
            }
            BLOCK8(tb)
        }

        fin_a = a7;      // alpha[255] on lane 31 (at scale 2^e)
        fin_c = a256;    // alpha[256] on lane 31
        fin_e = e;
    }

    __syncthreads();
    if (wrp == 0 && lane == 31) {
        float ll = __logf(fin_a + fin_c) + (float)fin_e * 0.6931471805599453f
                   - s_zsum;
        out[b] = -ll;
    }
}

extern "C" void kernel_launch(void* const* d_in, const int* in_sizes, int n_in,
                              void* d_out, int out_size)
{
    const int* y_true;
    const float* y_pred;
    if (in_sizes[0] == 128 * L_) {            // y_true: [B,L] int32
        y_true = (const int*)d_in[0];
        y_pred = (const float*)d_in[1];
    } else {
        y_true = (const int*)d_in[1];
        y_pred = (const float*)d_in[0];
    }
    const int B = out_size;                    // [B,1] float32
    ctc_bfp4_kernel<<<B, 64>>>(y_true, y_pred, (float*)d_out);
}

// round 6
// speedup vs baseline: 5.2157x; 1.0315x over previous
#include <cuda_runtime.h>

// CTC forward loss — linear-domain DP, per-lane block-floating-point scaling.
// B=128, T=1024, C=128 (blank=127), L=128, S=257.
//
// One CTA (64 threads) per batch element.
//   warp 0: sequential DP, lane l owns states 8l..8l+7 (+256 on lane 31).
//           true_alpha = a * 2^e.  Cross-lane handoff pm1 is PREPARED ONE
//           STEP AHEAD (shfl latency hidden). The exponent-gap scale sc_pm
//           is exact between renorms because e only changes at renorms.
//           RENORM EVERY 4 STEPS: worst-case decay 4*23.25 = 93 bits keeps
//           the lane max normal (no spurious "empty" lanes, no inf/NaN).
//   warp 1: softmax log-normalizer zsum = sum_t log(sum_c p + C*eps).
//
// loglik = log(a255+a256) + e*ln2 - zsum  (lane 31);  out = -loglik.

#define T_   1024
#define C_   128
#define L_   128
#define EPS_ 1e-7f
#define CEPS_ (128.0f * 1e-7f)
#define FULL 0xffffffffu

// One DP timestep. PH = ring slot (compile-time), RS = renorm, RF = refill.
// Uses pm1 prepared by the previous step; prepares pm1 for the next step.
#define STEP(PH, t, RS, RF) {                                                  \
    const float q0 = gbr[PH][0], q1 = gbr[PH][1],                              \
                q2 = gbr[PH][2], q3 = gbr[PH][3];                              \
    const float pb = pbr[PH];                                                  \
    if (RF) {                                                                  \
        const float* r8 = row + (size_t)((t) + 8) * C_;                        \
        gbr[PH][0] = r8[cls0] + EPS_; gbr[PH][1] = r8[cls1] + EPS_;            \
        gbr[PH][2] = r8[cls2] + EPS_; gbr[PH][3] = r8[cls3] + EPS_;            \
        pbr[PH]    = r8[C_ - 1] + EPS_;                                        \
    }                                                                          \
    const float n0 = (a0 + pm1) * pb;                                          \
    const float n1 = fmaf(sk0, pm1, a1 + a0) * q0;                             \
    const float n2 = (a2 + a1) * pb;                                           \
    const float n3 = fmaf(sk1, a1, a3 + a2) * q1;                              \
    const float n4 = (a4 + a3) * pb;                                           \
    const float n5 = fmaf(sk2, a3, a5 + a4) * q2;                              \
    const float n6 = (a6 + a5) * pb;                                           \
    const float n7 = fmaf(sk3, a5, a7 + a6) * q3;                              \
    const float n8 = (a256 + a7) * pb;   /* lane31: a7 == alpha[255] */        \
    if (RS) {                                                                  \
        float m = fmaxf(fmaxf(fmaxf(n0, n1), fmaxf(n2, n3)),                   \
                        fmaxf(fmaxf(n4, n5), fmaxf(n6, n7)));                  \
        if (lane == 31) m = fmaxf(m, n8);                                      \
        const int e_up_old = __shfl_up_sync(FULL, e, 1);                       \
        const bool has = (m > 0.f);                                            \
        const int k = has ? ((__float_as_int(m) >> 23) - 127) : 0;             \
        e = has ? (e + k) : e_up_old;    /* empty lane adopts neighbor */      \
        const float sck = __int_as_float((127 - k) << 23);                     \
        a0 = n0 * sck; a1 = n1 * sck; a2 = n2 * sck; a3 = n3 * sck;            \
        a4 = n4 * sck; a5 = n5 * sck; a6 = n6 * sck; a7 = n7 * sck;            \
        a256 = n8 * sck;                                                       \
        const int e_up2 = __shfl_up_sync(FULL, e, 1);                          \
        const int bexp = min(max(e_up2 - e + 127, 0), 254);                    \
        sc_pm = (lane == 0) ? 0.f : __int_as_float(bexp << 23);                \
    } else {                                                                   \
        a0 = n0; a1 = n1; a2 = n2; a3 = n3;                                    \
        a4 = n4; a5 = n5; a6 = n6; a7 = n7; a256 = n8;                         \
    }                                                                          \
    /* prepare next step's cross-lane operand (shfl latency hidden) */         \
    pm1 = __shfl_up_sync(FULL, a7, 1) * sc_pm;                                 \
    }

#define BLOCK8(tb, RF) \
    STEP(0, (tb) + 0, 0, RF) STEP(1, (tb) + 1, 0, RF) \
    STEP(2, (tb) + 2, 0, RF) STEP(3, (tb) + 3, 1, RF) \
    STEP(4, (tb) + 4, 0, RF) STEP(5, (tb) + 5, 0, RF) \
    STEP(6, (tb) + 6, 0, RF) STEP(7, (tb) + 7, 1, RF)

__global__ __launch_bounds__(64, 1)
void ctc_pipe4_kernel(const int* __restrict__ y_true,
                      const float* __restrict__ y_pred,
                      float* __restrict__ out)
{
    const int b    = blockIdx.x;
    const int tid  = threadIdx.x;
    const int lane = tid & 31;
    const int wrp  = tid >> 5;
    const float* __restrict__ row = y_pred + (size_t)b * T_ * C_;

    __shared__ float s_zsum;

    float fin_a = 0.f, fin_c = 0.f;
    int   fin_e = 0;

    if (wrp == 1) {
        // -------- softmax log-normalizer (DP-independent) --------
        float zs = 0.f;
        for (int t8 = 0; t8 < T_; t8 += 8) {
            float zp = 1.f;
            #pragma unroll
            for (int j = 0; j < 8; j++) {
                float4 v = *(const float4*)(row + (size_t)(t8 + j) * C_ + 4 * lane);
                float z = (v.x + v.y) + (v.z + v.w);
                z += __shfl_xor_sync(FULL, z, 1);
                z += __shfl_xor_sync(FULL, z, 2);
                z += __shfl_xor_sync(FULL, z, 4);
                z += __shfl_xor_sync(FULL, z, 8);
                z += __shfl_xor_sync(FULL, z, 16);
                zp *= (z + CEPS_);
            }
            zs += __logf(zp);
        }
        if (lane == 0) s_zsum = zs;
    } else {
        // -------- sequential DP warp --------
        int4 c4 = *(const int4*)(y_true + b * L_ + 4 * lane);
        const int cls0 = c4.x, cls1 = c4.y, cls2 = c4.z, cls3 = c4.w;
        int clsm1 = __shfl_up_sync(FULL, cls3, 1);
        const float sk0 = (lane > 0 && cls0 != clsm1) ? 1.f : 0.f;
        const float sk1 = (cls1 != cls0) ? 1.f : 0.f;
        const float sk2 = (cls2 != cls1) ? 1.f : 0.f;
        const float sk3 = (cls3 != cls2) ? 1.f : 0.f;

        // prefetch ring, depth 8: gbr[t&7] = p[t,cls*]+eps, pbr = p_blank+eps
        float gbr[8][4];
        float pbr[8];
        #pragma unroll
        for (int j = 0; j < 8; j++) {
            const float* r = row + (size_t)j * C_;
            gbr[j][0] = r[cls0] + EPS_; gbr[j][1] = r[cls1] + EPS_;
            gbr[j][2] = r[cls2] + EPS_; gbr[j][3] = r[cls3] + EPS_;
            pbr[j]    = r[C_ - 1] + EPS_;
        }

        float a0 = 0.f, a1 = 0.f, a2 = 0.f, a3 = 0.f,
              a4 = 0.f, a5 = 0.f, a6 = 0.f, a7 = 0.f, a256 = 0.f;
        int   e = 0;
        float sc_pm, pm1;

        // ---- t = 0 init: states 0 (blank) and 1 (first label) ----
        {
            if (lane == 0) { a0 = pbr[0]; a1 = gbr[0][0]; }
            const float* r8 = row + (size_t)8 * C_;   // refill slot 0
            gbr[0][0] = r8[cls0] + EPS_; gbr[0][1] = r8[cls1] + EPS_;
            gbr[0][2] = r8[cls2] + EPS_; gbr[0][3] = r8[cls3] + EPS_;
            pbr[0]    = r8[C_ - 1] + EPS_;
            // e == 0 on all lanes: exponent gap 0 -> scale 1 (0 on lane 0)
            sc_pm = (lane == 0) ? 0.f : 1.0f;
            pm1 = __shfl_up_sync(FULL, a7, 1) * sc_pm;   // = 0
        }

        // ---- t = 1..7 prologue (renorm at t=3 and t=7) ----
        STEP(1, 1, 0, 1) STEP(2, 2, 0, 1) STEP(3, 3, 1, 1) STEP(4, 4, 0, 1)
        STEP(5, 5, 0, 1) STEP(6, 6, 0, 1) STEP(7, 7, 1, 1)

        // ---- t = 8..1015: refills always in range (t+8 <= 1023) ----
        for (int tb = 8; tb < 1016; tb += 8) {
            BLOCK8(tb, 1)
        }
        // ---- t = 1016..1023: no refills ----
        BLOCK8(1016, 0)

        fin_a = a7;      // alpha[255] on lane 31 (scale 2^e)
        fin_c = a256;    // alpha[256] on lane 31
        fin_e = e;
    }

    __syncthreads();
    if (wrp == 0 && lane == 31) {
        float ll = __logf(fin_a + fin_c) + (float)fin_e * 0.6931471805599453f
                   - s_zsum;
        out[b] = -ll;
    }
}

extern "C" void kernel_launch(void* const* d_in, const int* in_sizes, int n_in,
                              void* d_out, int out_size)
{
    const int* y_true;
    const float* y_pred;
    if (in_sizes[0] == 128 * L_) {            // y_true: [B,L] int32
        y_true = (const int*)d_in[0];
        y_pred = (const float*)d_in[1];
    } else {
        y_true = (const int*)d_in[1];
        y_pred = (const float*)d_in[0];
    }
    const int B = out_size;                    // [B,1] float32
    ctc_pipe4_kernel<<<B, 64>>>(y_true, y_pred, (float*)d_out);
}

// round 7
// speedup vs baseline: 5.9978x; 1.1499x over previous
#include <cuda_runtime.h>

// CTC forward loss — linear-domain DP, per-lane block-floating-point scaling.
// B=128, T=1024, C=128 (blank=127), L=128, S=257.
//
// One CTA (64 threads) per batch element.
//   warp 0: sequential DP, lane l owns states 8l..8l+7 (+256 on lane 31).
//           true_alpha = a * 2^e. pm1 prepared one step ahead (shfl hidden).
//           Renorm every 4 steps; the scale sck is FOLDED INTO THE NEXT
//           STEP'S EMISSION PROBS (off the critical chain) instead of
//           rescaling the 9 states.
//   warp 1: softmax log-normalizer, quarter-warp-per-row layout:
//           4 rows in flight, 8 lanes per row, 3-shfl reduction,
//           4-round register prefetch ring (16 rows ahead).
//
// loglik = log(a255+a256) + e*ln2 - zsum  (lane 31);  out = -loglik.

#define T_   1024
#define C_   128
#define L_   128
#define EPS_ 1e-7f
#define CEPS_ (128.0f * 1e-7f)
#define FULL 0xffffffffu

// One DP timestep. PH = ring slot (compile-time), RS = renorm, RF = refill.
// pm1 (cross-lane operand) was prepared by the previous step; this step
// prepares the next one. Renorm scale is applied to slot (PH+1)'s emissions.
#define STEP(PH, t, RS, RF) {                                                  \
    const float q0 = gbr[PH][0], q1 = gbr[PH][1],                              \
                q2 = gbr[PH][2], q3 = gbr[PH][3];                              \
    const float pb = pbr[PH];                                                  \
    if (RF) {                                                                  \
        const float* r8 = row + (size_t)((t) + 8) * C_;                        \
        gbr[PH][0] = r8[cls0] + EPS_; gbr[PH][1] = r8[cls1] + EPS_;            \
        gbr[PH][2] = r8[cls2] + EPS_; gbr[PH][3] = r8[cls3] + EPS_;            \
        pbr[PH]    = r8[C_ - 1] + EPS_;                                        \
    }                                                                          \
    const float n0 = (a0 + pm1) * pb;                                          \
    const float n1 = fmaf(sk0, pm1, a1 + a0) * q0;                             \
    const float n2 = (a2 + a1) * pb;                                           \
    const float n3 = fmaf(sk1, a1, a3 + a2) * q1;                              \
    const float n4 = (a4 + a3) * pb;                                           \
    const float n5 = fmaf(sk2, a3, a5 + a4) * q2;                              \
    const float n6 = (a6 + a5) * pb;                                           \
    const float n7 = fmaf(sk3, a5, a7 + a6) * q3;                              \
    const float n8 = (a256 + a7) * pb;   /* lane31: a7 == alpha[255] */        \
    a0 = n0; a1 = n1; a2 = n2; a3 = n3;                                        \
    a4 = n4; a5 = n5; a6 = n6; a7 = n7; a256 = n8;                             \
    /* next step's cross-lane operand — OLD sc_pm is correct here */           \
    pm1 = __shfl_up_sync(FULL, a7, 1) * sc_pm;                                 \
    if (RS) {                                                                  \
        float m = fmaxf(fmaxf(fmaxf(n0, n1), fmaxf(n2, n3)),                   \
                        fmaxf(fmaxf(n4, n5), fmaxf(n6, n7)));                  \
        if (lane == 31) m = fmaxf(m, n8);                                      \
        const int e_up_old = __shfl_up_sync(FULL, e, 1);                       \
        const bool has = (m > 0.f);                                            \
        const int k = has ? ((__float_as_int(m) >> 23) - 127) : 0;             \
        e = has ? (e + k) : e_up_old;    /* empty lane adopts neighbor */      \
        const float sck = __int_as_float((127 - k) << 23);                     \
        const int NP = ((PH) + 1) & 7;   /* fold scale into next emissions */  \
        gbr[NP][0] *= sck; gbr[NP][1] *= sck;                                  \
        gbr[NP][2] *= sck; gbr[NP][3] *= sck;                                  \
        pbr[NP]    *= sck;                                                     \
        const int e_up2 = __shfl_up_sync(FULL, e, 1);                          \
        const int bexp = min(max(e_up2 - e + 127, 0), 254);                    \
        sc_pm = (lane == 0) ? 0.f : __int_as_float(bexp << 23);                \
    } }

#define BLOCK8(tb, RF) \
    STEP(0, (tb) + 0, 0, RF) STEP(1, (tb) + 1, 0, RF) \
    STEP(2, (tb) + 2, 0, RF) STEP(3, (tb) + 3, 1, RF) \
    STEP(4, (tb) + 4, 0, RF) STEP(5, (tb) + 5, 0, RF) \
    STEP(6, (tb) + 6, 0, RF) STEP(7, (tb) + 7, 1, RF)

// Final block: NO renorm at t=1023 so the outputs stay in the e-consistent
// scale set by the t=1019 renorm.
#define BLOCK8_LAST(tb) \
    STEP(0, (tb) + 0, 0, 0) STEP(1, (tb) + 1, 0, 0) \
    STEP(2, (tb) + 2, 0, 0) STEP(3, (tb) + 3, 1, 0) \
    STEP(4, (tb) + 4, 0, 0) STEP(5, (tb) + 5, 0, 0) \
    STEP(6, (tb) + 6, 0, 0) STEP(7, (tb) + 7, 0, 0)

__global__ __launch_bounds__(64, 1)
void ctc_fold_kernel(const int* __restrict__ y_true,
                     const float* __restrict__ y_pred,
                     float* __restrict__ out)
{
    const int b    = blockIdx.x;
    const int tid  = threadIdx.x;
    const int lane = tid & 31;
    const int wrp  = tid >> 5;
    const float* __restrict__ row = y_pred + (size_t)b * T_ * C_;

    __shared__ float s_zsum;

    float fin_a = 0.f, fin_c = 0.f;
    int   fin_e = 0;

    if (wrp == 1) {
        // -------- softmax log-normalizer: 4 rows per round --------
        // lane = 8*g + il : group g handles row (round*4 + g), lane sums
        // floats [16*il .. 16*il+15]. 3-shfl reduction within the group.
        const int g  = lane >> 3;
        const int il = lane & 7;
        const float* zrow = row + (size_t)g * C_ + (size_t)il * 16;

        float4 ring[4][4];
        #pragma unroll
        for (int j = 0; j < 4; j++) {
            const float* p = zrow + (size_t)j * 4 * C_;
            ring[j][0] = *(const float4*)(p + 0);
            ring[j][1] = *(const float4*)(p + 4);
            ring[j][2] = *(const float4*)(p + 8);
            ring[j][3] = *(const float4*)(p + 12);
        }

        float zs = 0.f;
        for (int r8 = 0; r8 < 256; r8 += 8) {
            float zp = 1.f;
            #pragma unroll
            for (int rr = 0; rr < 8; rr++) {
                const int slot = rr & 3;
                float4 v0 = ring[slot][0], v1 = ring[slot][1],
                       v2 = ring[slot][2], v3 = ring[slot][3];
                const int r = r8 + rr;
                if (r + 4 < 256) {
                    const float* p = zrow + (size_t)(r + 4) * 4 * C_;
                    ring[slot][0] = *(const float4*)(p + 0);
                    ring[slot][1] = *(const float4*)(p + 4);
                    ring[slot][2] = *(const float4*)(p + 8);
                    ring[slot][3] = *(const float4*)(p + 12);
                }
                float s = ((v0.x + v0.y) + (v0.z + v0.w))
                        + ((v1.x + v1.y) + (v1.z + v1.w))
                        + ((v2.x + v2.y) + (v2.z + v2.w))
                        + ((v3.x + v3.y) + (v3.z + v3.w));
                s += __shfl_xor_sync(FULL, s, 1);
                s += __shfl_xor_sync(FULL, s, 2);
                s += __shfl_xor_sync(FULL, s, 4);
                zp *= (s + CEPS_);      // 8 Z's of ~2^6 each: no overflow
            }
            zs += __logf(zp);
        }
        // combine the 4 groups' partial log-sums
        zs += __shfl_xor_sync(FULL, zs, 8);
        zs += __shfl_xor_sync(FULL, zs, 16);
        if (lane == 0) s_zsum = zs;
    } else {
        // -------- sequential DP warp --------
        int4 c4 = *(const int4*)(y_true + b * L_ + 4 * lane);
        const int cls0 = c4.x, cls1 = c4.y, cls2 = c4.z, cls3 = c4.w;
        int clsm1 = __shfl_up_sync(FULL, cls3, 1);
        const float sk0 = (lane > 0 && cls0 != clsm1) ? 1.f : 0.f;
        const float sk1 = (cls1 != cls0) ? 1.f : 0.f;
        const float sk2 = (cls2 != cls1) ? 1.f : 0.f;
        const float sk3 = (cls3 != cls2) ? 1.f : 0.f;

        // prefetch ring, depth 8: gbr[t&7] = p[t,cls*]+eps, pbr = p_blank+eps
        float gbr[8][4];
        float pbr[8];
        #pragma unroll
        for (int j = 0; j < 8; j++) {
            const float* r = row + (size_t)j * C_;
            gbr[j][0] = r[cls0] + EPS_; gbr[j][1] = r[cls1] + EPS_;
            gbr[j][2] = r[cls2] + EPS_; gbr[j][3] = r[cls3] + EPS_;
            pbr[j]    = r[C_ - 1] + EPS_;
        }

        float a0 = 0.f, a1 = 0.f, a2 = 0.f, a3 = 0.f,
              a4 = 0.f, a5 = 0.f, a6 = 0.f, a7 = 0.f, a256 = 0.f;
        int   e = 0;
        float sc_pm, pm1;

        // ---- t = 0 init: states 0 (blank) and 1 (first label) ----
        {
            if (lane == 0) { a0 = pbr[0]; a1 = gbr[0][0]; }
            const float* r8 = row + (size_t)8 * C_;   // refill slot 0
            gbr[0][0] = r8[cls0] + EPS_; gbr[0][1] = r8[cls1] + EPS_;
            gbr[0][2] = r8[cls2] + EPS_; gbr[0][3] = r8[cls3] + EPS_;
            pbr[0]    = r8[C_ - 1] + EPS_;
            // e == 0 on all lanes: exponent gap 0 -> scale 1 (0 on lane 0)
            sc_pm = (lane == 0) ? 0.f : 1.0f;
            pm1 = __shfl_up_sync(FULL, a7, 1) * sc_pm;   // = 0
        }

        // ---- t = 1..7 prologue (renorm at t=3 and t=7) ----
        STEP(1, 1, 0, 1) STEP(2, 2, 0, 1) STEP(3, 3, 1, 1) STEP(4, 4, 0, 1)
        STEP(5, 5, 0, 1) STEP(6, 6, 0, 1) STEP(7, 7, 1, 1)

        // ---- t = 8..1015: refills in range (t+8 <= 1023) ----
        for (int tb = 8; tb < 1016; tb += 8) {
            BLOCK8(tb, 1)
        }
        // ---- t = 1016..1023: no refills, no final renorm ----
        BLOCK8_LAST(1016)

        fin_a = a7;      // alpha[255] on lane 31 (scale 2^e)
        fin_c = a256;    // alpha[256] on lane 31
        fin_e = e;
    }

    __syncthreads();
    if (wrp == 0 && lane == 31) {
        float ll = __logf(fin_a + fin_c) + (float)fin_e * 0.6931471805599453f
                   - s_zsum;
        out[b] = -ll;
    }
}

extern "C" void kernel_launch(void* const* d_in, const int* in_sizes, int n_in,
                              void* d_out, int out_size)
{
    const int* y_true;
    const float* y_pred;
    if (in_sizes[0] == 128 * L_) {            // y_true: [B,L] int32
        y_true = (const int*)d_in[0];
        y_pred = (const float*)d_in[1];
    } else {
        y_true = (const int*)d_in[1];
        y_pred = (const float*)d_in[0];
    }
    const int B = out_size;                    // [B,1] float32
    ctc_fold_kernel<<<B, 64>>>(y_true, y_pred, (float*)d_out);
}